// round 4
// baseline (speedup 1.0000x reference)
#include <cuda_runtime.h>

// Problem constants (fixed by the reference: B=8, H=W=512, C=32, n_segments=256)
#define HW_   (512 * 512)      // pixels per batch = 262144 = 2^18
#define B_    8
#define C_    32
#define S_    256
#define NBUCK (B_ * S_)        // 2048 (batch, segment) buckets
#define CAP   2048             // slots per bucket (mean occupancy ~1020, >30 sigma margin)

// Scratch: bucket cursors + pixel-index lists. __device__ globals (no allocs allowed).
__device__ int g_cursor[NBUCK];
__device__ int g_list[(size_t)NBUCK * CAP];   // 16 MB

// ---------------------------------------------------------------------------
// Kernel 1: zero the bucket cursors (must be re-done every launch; graph replays).
// ---------------------------------------------------------------------------
__global__ void k_zero() {
    int i = blockIdx.x * blockDim.x + threadIdx.x;
    if (i < NBUCK) g_cursor[i] = 0;
}

// ---------------------------------------------------------------------------
// Kernel 2: bucket pixels by (batch, segment). One global atomic per pixel,
// spread over 2048 addresses -> pipelines through the L2 atomic ALUs.
// ---------------------------------------------------------------------------
__global__ void k_bucket(const int* __restrict__ slic) {
    int stride = gridDim.x * blockDim.x;
    for (int i = blockIdx.x * blockDim.x + threadIdx.x; i < B_ * HW_; i += stride) {
        int s = slic[i] - 1;                       // 1-based ids; 0 -> -1 dropped
        if ((unsigned)s < (unsigned)S_) {
            int bucket = ((i >> 18) << 8) | s;     // (batch << 8) | segment
            int pos = atomicAdd(&g_cursor[bucket], 1);
            if (pos < CAP)
                g_list[((size_t)bucket << 11) + pos] = i & (HW_ - 1);  // local pixel idx
        }
    }
}

// ---------------------------------------------------------------------------
// Kernel 3: per-bucket reduction. 1 CTA per (batch, segment), 4 warps.
// lane = channel -> each pixel's 32-float row is exactly one coalesced 128B line.
// Register accumulation, no atomics. Indices broadcast via shfl from a
// coalesced 32-wide list load. Fully unrolled 32-pixel body for MLP.
// ---------------------------------------------------------------------------
__global__ void __launch_bounds__(128) k_sum(const float* __restrict__ img,
                                             float* __restrict__ out) {
    int bucket = blockIdx.x;
    int b = bucket >> 8;
    int s = bucket & (S_ - 1);
    int n = min(g_cursor[bucket], CAP);
    const int*   __restrict__ lst = g_list + ((size_t)bucket << 11);
    const float* __restrict__ im  = img + (size_t)b * HW_ * C_;

    int lane = threadIdx.x & 31;
    int w    = threadIdx.x >> 5;

    float sum = 0.0f;
    int   cnt = 0;

    for (int base = w * 32; base < n; base += 128) {
        int m = n - base;
        int idx = (lane < m) ? lst[base + lane] : 0;   // coalesced 128B list load
        if (m >= 32) {
            #pragma unroll
            for (int j = 0; j < 32; j++) {
                int p = __shfl_sync(0xffffffffu, idx, j);
                float v = __ldg(im + (size_t)p * C_ + lane);  // 128B line, full use
                sum += v;
                cnt += (v != 0.0f);
            }
        } else {
            for (int j = 0; j < m; j++) {
                int p = __shfl_sync(0xffffffffu, idx, j);
                float v = __ldg(im + (size_t)p * C_ + lane);
                sum += v;
                cnt += (v != 0.0f);
            }
        }
    }

    // Cross-warp reduction (4 partials per channel).
    __shared__ float ssum[4][32];
    __shared__ int   scnt[4][32];
    ssum[w][lane] = sum;
    scnt[w][lane] = cnt;
    __syncthreads();

    if (w == 0) {
        float t  = ssum[0][lane] + ssum[1][lane] + ssum[2][lane] + ssum[3][lane];
        int   c4 = scnt[0][lane] + scnt[1][lane] + scnt[2][lane] + scnt[3][lane];
        // 0/0 -> NaN matches the reference (sums/cnts with cnt==0).
        out[((size_t)s * B_ + b) * C_ + lane] = t / (float)c4;
    }
}

// ---------------------------------------------------------------------------
// Launch: three kernels on the default stream (serialized, graph-capturable).
// d_in[0] = image_output [8,512,512,32] f32
// d_in[1] = slic_output  [8,512,512,1]  i32
// d_in[2] = n_segments (scalar, fixed 256 -> compiled in)
// d_out   = [256, 8, 32] f32
// ---------------------------------------------------------------------------
extern "C" void kernel_launch(void* const* d_in, const int* in_sizes, int n_in,
                              void* d_out, int out_size) {
    const float* img  = (const float*)d_in[0];
    const int*   slic = (const int*)d_in[1];
    float*       out  = (float*)d_out;

    k_zero<<<(NBUCK + 255) / 256, 256>>>();
    k_bucket<<<2048, 256>>>(slic);
    k_sum<<<NBUCK, 128>>>(img, out);
}

// round 5
// speedup vs baseline: 1.1178x; 1.1178x over previous
#include <cuda_runtime.h>

// Problem constants (fixed by the reference: B=8, H=W=512, C=32, n_segments=256)
#define B_    8
#define HW_   (512 * 512)            // 262144 pixels per batch
#define C_    32
#define S_    256
#define CHUNKS_PER_BATCH 64
#define NCTA  (B_ * CHUNKS_PER_BATCH)   // 512 CTAs, one contiguous chunk each
#define CHUNK (HW_ / CHUNKS_PER_BATCH)  // 4096 pixels
#define WARPS 8
#define SEGW  (S_ / WARPS)              // 32 segments owned per warp

// Partial results scratch (overwritten fully every launch -> no zeroing needed,
// no cross-replay state, fully deterministic: zero atomics in this kernel).
__device__ float          g_psum[(size_t)NCTA * S_ * C_];   // 16 MB
__device__ unsigned short g_pcnt[(size_t)NCTA * S_ * C_];   //  8 MB

// ---------------------------------------------------------------------------
// Kernel 1: sequential stream over the image. Warp-private smem accumulators,
// segment ownership partitioned by warp -> no atomics, no races.
// smem: fp32 sums [8][32][32] (32 KB) + u16 counts [8][32][32] (16 KB) = 48 KB.
// 4 CTAs/SM -> all 512 CTAs resident in a single wave.
// ---------------------------------------------------------------------------
__global__ void __launch_bounds__(256) k_accum(const float* __restrict__ img,
                                               const int* __restrict__ slic) {
    extern __shared__ char smem[];
    float*          s_sum = (float*)smem;                         // 8*32*32 f32
    unsigned short* s_cnt = (unsigned short*)(smem + WARPS * SEGW * C_ * 4);

    const int tid  = threadIdx.x;
    const int w    = tid >> 5;
    const int lane = tid & 31;
    const int lo   = w * SEGW;

    for (int i = tid; i < WARPS * SEGW * C_; i += 256) { s_sum[i] = 0.f; s_cnt[i] = 0; }
    __syncthreads();

    const size_t pix0 = (size_t)blockIdx.x * CHUNK;   // linear pixel base (covers batch too)
    float*          wsum = s_sum + w * SEGW * C_;
    unsigned short* wcnt = s_cnt + w * SEGW * C_;

    for (int base = 0; base < CHUNK; base += 32) {
        // Coalesced id load; the 8 warps share these lines via L1.
        int id = slic[pix0 + base + lane] - 1;              // 1-based; 0 -> -1 dropped
        bool mine = ((unsigned)(id - lo)) < (unsigned)SEGW;
        unsigned mask = __ballot_sync(0xffffffffu, mine);

        while (mask) {
            // Batch up to 8 owned pixels: issue all 8 independent 128B row
            // loads before consuming -> MLP ~8 per warp.
            int js[8]; float vs[8]; int n = 0;
            #pragma unroll
            for (int t = 0; t < 8; t++) {
                js[t] = 0;
                if (mask) { js[t] = __ffs(mask) - 1; mask &= mask - 1; n = t + 1; }
            }
            #pragma unroll
            for (int t = 0; t < 8; t++)
                if (t < n)
                    vs[t] = __ldg(img + (pix0 + base + js[t]) * C_ + lane); // full 128B line
            #pragma unroll
            for (int t = 0; t < 8; t++)
                if (t < n) {
                    int segl = __shfl_sync(0xffffffffu, id, js[t]) - lo;    // js uniform
                    float v = vs[t];
                    wsum[segl * C_ + lane] += v;                // conflict-free (lane=bank)
                    wcnt[segl * C_ + lane] += (v != 0.0f);      // per-channel nonzero count
                }
        }
    }

    // Write this chunk's partials (warp-private -> no sync needed before read).
    const size_t ob = (size_t)blockIdx.x * S_ * C_;
    #pragma unroll 4
    for (int segl = 0; segl < SEGW; segl++) {
        g_psum[ob + (lo + segl) * C_ + lane] = wsum[segl * C_ + lane];
        g_pcnt[ob + (lo + segl) * C_ + lane] = wcnt[segl * C_ + lane];
    }
}

// ---------------------------------------------------------------------------
// Kernel 2: reduce 64 chunk-partials per (batch, segment) and divide.
// grid = 2048 warps, lane = channel. 24 MB scratch read, fixed order ->
// deterministic. 0/0 -> NaN matches the reference for empty segments.
// ---------------------------------------------------------------------------
__global__ void __launch_bounds__(32) k_final(float* __restrict__ out) {
    int bs = blockIdx.x;            // b*256 + s
    int b = bs >> 8, s = bs & (S_ - 1);
    int lane = threadIdx.x;

    float sum = 0.0f;
    int   cnt = 0;
    #pragma unroll 8
    for (int k = 0; k < CHUNKS_PER_BATCH; k++) {
        size_t idx = ((size_t)(b * CHUNKS_PER_BATCH + k) * S_ + s) * C_ + lane;
        sum += g_psum[idx];
        cnt += (int)g_pcnt[idx];
    }
    out[((size_t)s * B_ + b) * C_ + lane] = sum / (float)cnt;
}

// ---------------------------------------------------------------------------
// d_in[0] = image_output [8,512,512,32] f32 (contiguous -> linear pixel rows)
// d_in[1] = slic_output  [8,512,512,1]  i32
// d_in[2] = n_segments (fixed 256, compiled in)
// d_out   = [256, 8, 32] f32
// ---------------------------------------------------------------------------
extern "C" void kernel_launch(void* const* d_in, const int* in_sizes, int n_in,
                              void* d_out, int out_size) {
    const float* img  = (const float*)d_in[0];
    const int*   slic = (const int*)d_in[1];
    float*       out  = (float*)d_out;

    const int smem_bytes = WARPS * SEGW * C_ * (4 + 2);   // 49152
    cudaFuncSetAttribute(k_accum, cudaFuncAttributeMaxDynamicSharedMemorySize, smem_bytes);

    k_accum<<<NCTA, 256, smem_bytes>>>(img, slic);
    k_final<<<B_ * S_, 32>>>(out);
}